// round 5
// baseline (speedup 1.0000x reference)
#include <cuda_runtime.h>

#define N_NODES  50000
#define N_EDGES  800000
#define N_GRAPHS 64
#define NEG      0.2f

// ---------------- device scratch (no allocations allowed) ----------------
__device__ float4 g_x4[N_NODES];                  // (s1, x0, x1, x2)
__device__ float  g_d1[N_NODES];                  // d1 per node
__device__ float4 g_agg1[N_NODES];                // (sum, ax, ay, az)
__device__ float4 g_hA[N_NODES];                  // h0..h3
__device__ float4 g_hB[N_NODES];                  // h4..h7
__device__ float2 g_sd2[N_NODES];                 // (s2, d2)
__device__ float  g_sum2[N_NODES];                // layer2 sum accumulator
__device__ float4 g_aggA[N_NODES];                // layer2 h0..h3 accumulator
__device__ float4 g_aggB[N_NODES];                // layer2 h4..h7 accumulator
__device__ float  g_wa2[16];                      // wa_src2[8], wa_dst2[8]

__device__ __forceinline__ float lrelu(float v) { return v > 0.f ? v : NEG * v; }

__device__ __forceinline__ void red_add_v4(float4* addr, float a, float b, float c, float d) {
    asm volatile("red.global.add.v4.f32 [%0], {%1,%2,%3,%4};"
                 :: "l"(addr), "f"(a), "f"(b), "f"(c), "f"(d) : "memory");
}
__device__ __forceinline__ void red_add_f32(float* addr, float a) {
    asm volatile("red.global.add.f32 [%0], %1;"
                 :: "l"(addr), "f"(a) : "memory");
}

// -------- fused prep + layer1 node init (every block folds wa1 locally) --------
__global__ void __launch_bounds__(128) k_init(const float* __restrict__ x,
                      const float* __restrict__ W1, const float* __restrict__ as1,
                      const float* __restrict__ ad1,
                      const float* __restrict__ W2, const float* __restrict__ as2,
                      const float* __restrict__ ad2,
                      float* __restrict__ out) {
    __shared__ float swa[6];     // wa_src1[3], wa_dst1[3]
    int tid = threadIdx.x;
    if (tid < 6) {
        int c = tid % 3;
        const float* av = (tid < 3) ? as1 : ad1;
        float a = 0.f;
        #pragma unroll
        for (int j = 0; j < 8; j++) a += W1[c * 8 + j] * av[j];
        swa[tid] = a;
    }
    // block 0 extra duty: fold wa2 and zero the output
    if (blockIdx.x == 0) {
        if (tid < N_GRAPHS) out[tid] = 0.f;
        int w = tid >> 5, lane = tid & 31;
        #pragma unroll
        for (int kk = 0; kk < 2; kk++) {
            int k = w * 2 + kk;             // 4 warps x 2 = 8 rows
            float a = 0.f, b = 0.f;
            #pragma unroll
            for (int j = 0; j < 8; j++) {
                int f = lane * 8 + j;
                float wv = W2[k * 256 + f];
                a += wv * as2[f];
                b += wv * ad2[f];
            }
            #pragma unroll
            for (int o = 16; o > 0; o >>= 1) {
                a += __shfl_down_sync(0xffffffffu, a, o);
                b += __shfl_down_sync(0xffffffffu, b, o);
            }
            if (lane == 0) { g_wa2[k] = a; g_wa2[8 + k] = b; }
        }
    }
    __syncthreads();

    int v = blockIdx.x * 128 + tid;
    if (v >= N_NODES) return;
    float x0 = x[v * 3 + 0], x1 = x[v * 3 + 1], x2 = x[v * 3 + 2];
    float s = x0 * swa[0] + x1 * swa[1] + x2 * swa[2];
    float d = x0 * swa[3] + x1 * swa[4] + x2 * swa[5];
    g_x4[v] = make_float4(s, x0, x1, x2);
    g_d1[v] = d;
    g_agg1[v] = make_float4(0.f, 0.f, 0.f, 0.f);
}

// ---------------- layer1 edge pass: 2 edges/thread, v4 red ---------------------
__global__ void __launch_bounds__(256) k_edgeB1(const int* __restrict__ ei) {
    int p = blockIdx.x * blockDim.x + threadIdx.x;
    int i = p * 2;
    if (i >= N_EDGES) return;
    const int2 sp = *(const int2*)(ei + i);
    const int2 dp = *(const int2*)(ei + N_EDGES + i);
    float4 f0 = g_x4[sp.x];
    float4 f1 = g_x4[sp.y];
    float d0 = g_d1[dp.x];
    float d1v = g_d1[dp.y];
    float w0 = __expf(lrelu(f0.x + d0));
    float w1 = __expf(lrelu(f1.x + d1v));
    red_add_v4(&g_agg1[dp.x], w0, w0 * f0.y, w0 * f0.z, w0 * f0.w);
    red_add_v4(&g_agg1[dp.y], w1, w1 * f1.y, w1 * f1.z, w1 * f1.w);
}

// ------- layer1 finalize: self-loop, normalize, project W1, prep layer2 --------
__global__ void __launch_bounds__(128) k_node1_fin(const float* __restrict__ W1,
                                                   const float* __restrict__ b1) {
    int v = blockIdx.x * 128 + threadIdx.x;
    if (v >= N_NODES) return;
    float4 f = g_x4[v];
    float w = __expf(lrelu(f.x + g_d1[v]));       // self-loop weight
    float4 a = g_agg1[v];
    float inv = 1.f / (a.x + w);
    float t0 = (a.y + w * f.y) * inv;
    float t1 = (a.z + w * f.z) * inv;
    float t2 = (a.w + w * f.w) * inv;

    float y[8];
    float s2 = 0.f, d2 = 0.f;
    #pragma unroll
    for (int k = 0; k < 8; k++) {
        float t = t0 * W1[k] + t1 * W1[8 + k] + t2 * W1[16 + k] + b1[k];
        t = t > 0.f ? t : 0.f;                    // relu
        y[k] = t;
        s2 += t * g_wa2[k];
        d2 += t * g_wa2[8 + k];
    }
    g_hA[v] = make_float4(y[0], y[1], y[2], y[3]);
    g_hB[v] = make_float4(y[4], y[5], y[6], y[7]);
    g_sd2[v] = make_float2(s2, d2);
    g_sum2[v] = 0.f;
    g_aggA[v] = make_float4(0.f, 0.f, 0.f, 0.f);
    g_aggB[v] = make_float4(0.f, 0.f, 0.f, 0.f);
}

// ---------------- layer2 edge pass: 2 edges/thread, 2x v4 + scalar red ---------
__global__ void __launch_bounds__(256) k_edgeB2(const int* __restrict__ ei) {
    int p = blockIdx.x * blockDim.x + threadIdx.x;
    int i = p * 2;
    if (i >= N_EDGES) return;
    const int2 sp = *(const int2*)(ei + i);
    const int2 dp = *(const int2*)(ei + N_EDGES + i);

    float4 A0 = g_hA[sp.x];
    float4 B0 = g_hB[sp.x];
    float  s20 = g_sd2[sp.x].x;
    float  d20 = g_sd2[dp.x].y;
    float4 A1 = g_hA[sp.y];
    float4 B1 = g_hB[sp.y];
    float  s21 = g_sd2[sp.y].x;
    float  d21 = g_sd2[dp.y].y;

    float w0 = __expf(lrelu(s20 + d20));
    float w1 = __expf(lrelu(s21 + d21));

    red_add_f32(&g_sum2[dp.x], w0);
    red_add_v4(&g_aggA[dp.x], w0 * A0.x, w0 * A0.y, w0 * A0.z, w0 * A0.w);
    red_add_v4(&g_aggB[dp.x], w0 * B0.x, w0 * B0.y, w0 * B0.z, w0 * B0.w);
    red_add_f32(&g_sum2[dp.y], w1);
    red_add_v4(&g_aggA[dp.y], w1 * A1.x, w1 * A1.y, w1 * A1.z, w1 * A1.w);
    red_add_v4(&g_aggB[dp.y], w1 * B1.x, w1 * B1.y, w1 * B1.z, w1 * B1.w);
}

// -------- layer2 finalize + W2 projection + ReLU + FC + graph pooling ----------
__global__ void __launch_bounds__(128) k_node2_fin(const int* __restrict__ batch,
                            const float* __restrict__ W2,
                            const float* __restrict__ b2,
                            const float* __restrict__ fcw,
                            const float* __restrict__ fcb,
                            float* __restrict__ out) {
    __shared__ float4 sW2[512];   // [k][f/4] : k*64 + f4
    __shared__ float4 sb2[64];
    __shared__ float4 sfw[64];
    __shared__ float  sg[N_GRAPHS];

    int tid = threadIdx.x;
    for (int j = tid; j < 512; j += 128)
        sW2[j] = ((const float4*)W2)[j];
    for (int j = tid; j < 64; j += 128) {
        sb2[j] = ((const float4*)b2)[j];
        sfw[j] = ((const float4*)fcw)[j];
    }
    if (tid < N_GRAPHS) sg[tid] = 0.f;
    __syncthreads();

    int v = blockIdx.x * 128 + tid;
    if (v < N_NODES) {
        float4 A = g_hA[v];
        float4 B = g_hB[v];
        float2 sd = g_sd2[v];
        float w = __expf(lrelu(sd.x + sd.y));     // self-loop weight
        float4 aA = g_aggA[v];
        float4 aB = g_aggB[v];
        float inv = 1.f / (g_sum2[v] + w);
        float t[8];
        t[0] = (aA.x + w * A.x) * inv;
        t[1] = (aA.y + w * A.y) * inv;
        t[2] = (aA.z + w * A.z) * inv;
        t[3] = (aA.w + w * A.w) * inv;
        t[4] = (aB.x + w * B.x) * inv;
        t[5] = (aB.y + w * B.y) * inv;
        t[6] = (aB.z + w * B.z) * inv;
        t[7] = (aB.w + w * B.w) * inv;

        float acc = 0.f;
        #pragma unroll 4
        for (int f4 = 0; f4 < 64; f4++) {
            float4 y = sb2[f4];
            #pragma unroll
            for (int k = 0; k < 8; k++) {
                float4 wv = sW2[k * 64 + f4];
                y.x += t[k] * wv.x;
                y.y += t[k] * wv.y;
                y.z += t[k] * wv.z;
                y.w += t[k] * wv.w;
            }
            y.x = y.x > 0.f ? y.x : 0.f;
            y.y = y.y > 0.f ? y.y : 0.f;
            y.z = y.z > 0.f ? y.z : 0.f;
            y.w = y.w > 0.f ? y.w : 0.f;
            float4 fw = sfw[f4];
            acc += y.x * fw.x + y.y * fw.y + y.z * fw.z + y.w * fw.w;
        }
        acc += fcb[0];
        atomicAdd(&sg[batch[v]], acc);
    }
    __syncthreads();
    if (tid < N_GRAPHS) atomicAdd(&out[tid], sg[tid]);
}

// --------------------------------- launch --------------------------------------
extern "C" void kernel_launch(void* const* d_in, const int* in_sizes, int n_in,
                              void* d_out, int out_size) {
    const float* x     = (const float*)d_in[0];
    const int*   ei    = (const int*)d_in[1];     // int64 delivered as int32
    // d_in[2] = edge_attr (unused)
    const int*   batch = (const int*)d_in[3];
    const float* W1    = (const float*)d_in[4];
    const float* as1   = (const float*)d_in[5];
    const float* ad1   = (const float*)d_in[6];
    const float* b1    = (const float*)d_in[7];
    const float* W2    = (const float*)d_in[8];
    const float* as2   = (const float*)d_in[9];
    const float* ad2   = (const float*)d_in[10];
    const float* b2    = (const float*)d_in[11];
    const float* fcw   = (const float*)d_in[12];
    const float* fcb   = (const float*)d_in[13];
    float*       out   = (float*)d_out;

    const int EB2 = (N_EDGES / 2 + 255) / 256;  // 1563
    const int NB  = (N_NODES + 127) / 128;      // 391

    k_init<<<NB, 128>>>(x, W1, as1, ad1, W2, as2, ad2, out);
    k_edgeB1<<<EB2, 256>>>(ei);
    k_node1_fin<<<NB, 128>>>(W1, b1);
    k_edgeB2<<<EB2, 256>>>(ei);
    k_node2_fin<<<NB, 128>>>(batch, W2, b2, fcw, fcb, out);
}

// round 9
// speedup vs baseline: 1.5866x; 1.5866x over previous
#include <cuda_runtime.h>

#define N_NODES  50000
#define N_EDGES  800000
#define N_GRAPHS 64
#define NEG      0.2f

// ---------------- device scratch (no allocations allowed) ----------------
__device__ float4 g_x4[N_NODES];                      // (s1, x0, x1, x2)
__device__ float  g_d1[N_NODES];                      // d1 per node
__device__ float4 g_agg1[N_NODES];                    // (sum, ax, ay, az)
__device__ __align__(16) float g_h[N_NODES * 12];     // [s2, h0..h7, d2, pad2] 48B/node
__device__ __align__(16) float g_agg2[N_NODES * 12];  // [sum,-,-,-, a0..a3, a4..a7]
__device__ float  g_wa2[16];                          // wa_src2[8], wa_dst2[8]

__device__ __forceinline__ float lrelu(float v) { return v > 0.f ? v : NEG * v; }

__device__ __forceinline__ void red_add_v4(float* addr, float a, float b, float c, float d) {
    asm volatile("red.global.add.v4.f32 [%0], {%1,%2,%3,%4};"
                 :: "l"(addr), "f"(a), "f"(b), "f"(c), "f"(d) : "memory");
}
__device__ __forceinline__ void red_add_f32(float* addr, float a) {
    asm volatile("red.global.add.f32 [%0], %1;"
                 :: "l"(addr), "f"(a) : "memory");
}

// -------- fused prep + layer1 node init (every block folds wa1 locally) --------
__global__ void __launch_bounds__(128) k_init(const float* __restrict__ x,
                      const float* __restrict__ W1, const float* __restrict__ as1,
                      const float* __restrict__ ad1,
                      const float* __restrict__ W2, const float* __restrict__ as2,
                      const float* __restrict__ ad2,
                      float* __restrict__ out) {
    __shared__ float swa[6];     // wa_src1[3], wa_dst1[3]
    int tid = threadIdx.x;
    if (tid < 6) {
        int c = tid % 3;
        const float* av = (tid < 3) ? as1 : ad1;
        float a = 0.f;
        #pragma unroll
        for (int j = 0; j < 8; j++) a += W1[c * 8 + j] * av[j];
        swa[tid] = a;
    }
    // block 0 extra duty: fold wa2 and zero the output
    if (blockIdx.x == 0) {
        if (tid < N_GRAPHS) out[tid] = 0.f;
        int w = tid >> 5, lane = tid & 31;
        #pragma unroll
        for (int kk = 0; kk < 2; kk++) {
            int k = w * 2 + kk;             // 4 warps x 2 = 8 rows
            float a = 0.f, b = 0.f;
            #pragma unroll
            for (int j = 0; j < 8; j++) {
                int f = lane * 8 + j;
                float wv = W2[k * 256 + f];
                a += wv * as2[f];
                b += wv * ad2[f];
            }
            #pragma unroll
            for (int o = 16; o > 0; o >>= 1) {
                a += __shfl_down_sync(0xffffffffu, a, o);
                b += __shfl_down_sync(0xffffffffu, b, o);
            }
            if (lane == 0) { g_wa2[k] = a; g_wa2[8 + k] = b; }
        }
    }
    __syncthreads();

    int v = blockIdx.x * 128 + tid;
    if (v >= N_NODES) return;
    float x0 = x[v * 3 + 0], x1 = x[v * 3 + 1], x2 = x[v * 3 + 2];
    float s = x0 * swa[0] + x1 * swa[1] + x2 * swa[2];
    float d = x0 * swa[3] + x1 * swa[4] + x2 * swa[5];
    g_x4[v] = make_float4(s, x0, x1, x2);
    g_d1[v] = d;
    g_agg1[v] = make_float4(0.f, 0.f, 0.f, 0.f);
}

// ---------------- layer1 edge pass: exp(logit) + v4 scatter (R4 form) ----------
__global__ void __launch_bounds__(256) k_edgeB1(const int* __restrict__ ei) {
    int i = blockIdx.x * blockDim.x + threadIdx.x;
    if (i >= N_EDGES) return;
    int s = ei[i], d = ei[N_EDGES + i];
    float4 f = g_x4[s];
    float w = __expf(lrelu(f.x + g_d1[d]));
    red_add_v4((float*)&g_agg1[d], w, w * f.y, w * f.z, w * f.w);
}

// ------- layer1 finalize: self-loop, normalize, project W1, prep layer2 --------
__global__ void __launch_bounds__(128) k_node1_fin(const float* __restrict__ W1,
                                                   const float* __restrict__ b1) {
    int v = blockIdx.x * 128 + threadIdx.x;
    if (v >= N_NODES) return;
    float4 f = g_x4[v];
    float w = __expf(lrelu(f.x + g_d1[v]));       // self-loop weight
    float4 a = g_agg1[v];
    float inv = 1.f / (a.x + w);
    float t0 = (a.y + w * f.y) * inv;
    float t1 = (a.z + w * f.z) * inv;
    float t2 = (a.w + w * f.w) * inv;

    float y[8];
    float s2 = 0.f, d2 = 0.f;
    #pragma unroll
    for (int k = 0; k < 8; k++) {
        float t = t0 * W1[k] + t1 * W1[8 + k] + t2 * W1[16 + k] + b1[k];
        t = t > 0.f ? t : 0.f;                    // relu
        y[k] = t;
        s2 += t * g_wa2[k];
        d2 += t * g_wa2[8 + k];
    }
    float4* hv = (float4*)(g_h + v * 12);
    hv[0] = make_float4(s2, y[0], y[1], y[2]);
    hv[1] = make_float4(y[3], y[4], y[5], y[6]);
    hv[2] = make_float4(y[7], d2, 0.f, 0.f);
    float4* ag = (float4*)(g_agg2 + v * 12);
    ag[0] = make_float4(0.f, 0.f, 0.f, 0.f);
    ag[1] = make_float4(0.f, 0.f, 0.f, 0.f);
    ag[2] = make_float4(0.f, 0.f, 0.f, 0.f);
}

// ---------------- layer2 edge pass: exp + 2x v4 + scalar red (R4 form) ---------
__global__ void __launch_bounds__(256) k_edgeB2(const int* __restrict__ ei) {
    int i = blockIdx.x * blockDim.x + threadIdx.x;
    if (i >= N_EDGES) return;
    int s = ei[i], d = ei[N_EDGES + i];
    const float4* hp = (const float4*)(g_h + s * 12);
    float4 A = hp[0];                       // s2, h0, h1, h2
    float4 B = hp[1];                       // h3..h6
    float  h7 = g_h[s * 12 + 8];
    float  d2 = g_h[d * 12 + 9];
    float w = __expf(lrelu(A.x + d2));
    float* ag = g_agg2 + d * 12;
    red_add_f32(ag, w);
    red_add_v4(ag + 4, w * A.y, w * A.z, w * A.w, w * B.x);
    red_add_v4(ag + 8, w * B.y, w * B.z, w * B.w, w * h7);
}

// -------- layer2 finalize + W2 projection + ReLU + FC + graph pooling ----------
__global__ void __launch_bounds__(128) k_node2_fin(const int* __restrict__ batch,
                            const float* __restrict__ W2,
                            const float* __restrict__ b2,
                            const float* __restrict__ fcw,
                            const float* __restrict__ fcb,
                            float* __restrict__ out) {
    __shared__ float4 sW2[512];   // [k][f/4] : k*64 + f4
    __shared__ float4 sb2[64];
    __shared__ float4 sfw[64];
    __shared__ float  sg[N_GRAPHS];

    int tid = threadIdx.x;
    for (int j = tid; j < 512; j += 128)
        sW2[j] = ((const float4*)W2)[j];
    for (int j = tid; j < 64; j += 128) {
        sb2[j] = ((const float4*)b2)[j];
        sfw[j] = ((const float4*)fcw)[j];
    }
    if (tid < N_GRAPHS) sg[tid] = 0.f;
    __syncthreads();

    int v = blockIdx.x * 128 + tid;
    if (v < N_NODES) {
        const float4* hp = (const float4*)(g_h + v * 12);
        float4 A = hp[0];
        float4 B = hp[1];
        float4 C = hp[2];                         // h7, d2, -, -
        float w = __expf(lrelu(A.x + C.y));       // self-loop weight
        const float* ag = g_agg2 + v * 12;
        float inv = 1.f / (ag[0] + w);
        float t[8];
        t[0] = (ag[4]  + w * A.y) * inv;
        t[1] = (ag[5]  + w * A.z) * inv;
        t[2] = (ag[6]  + w * A.w) * inv;
        t[3] = (ag[7]  + w * B.x) * inv;
        t[4] = (ag[8]  + w * B.y) * inv;
        t[5] = (ag[9]  + w * B.z) * inv;
        t[6] = (ag[10] + w * B.w) * inv;
        t[7] = (ag[11] + w * C.x) * inv;

        float acc = 0.f;
        #pragma unroll 4
        for (int f4 = 0; f4 < 64; f4++) {
            float4 y = sb2[f4];
            #pragma unroll
            for (int k = 0; k < 8; k++) {
                float4 wv = sW2[k * 64 + f4];
                y.x += t[k] * wv.x;
                y.y += t[k] * wv.y;
                y.z += t[k] * wv.z;
                y.w += t[k] * wv.w;
            }
            y.x = y.x > 0.f ? y.x : 0.f;
            y.y = y.y > 0.f ? y.y : 0.f;
            y.z = y.z > 0.f ? y.z : 0.f;
            y.w = y.w > 0.f ? y.w : 0.f;
            float4 fw = sfw[f4];
            acc += y.x * fw.x + y.y * fw.y + y.z * fw.z + y.w * fw.w;
        }
        acc += fcb[0];
        atomicAdd(&sg[batch[v]], acc);
    }
    __syncthreads();
    if (tid < N_GRAPHS) atomicAdd(&out[tid], sg[tid]);
}

// --------------------------------- launch --------------------------------------
extern "C" void kernel_launch(void* const* d_in, const int* in_sizes, int n_in,
                              void* d_out, int out_size) {
    const float* x     = (const float*)d_in[0];
    const int*   ei    = (const int*)d_in[1];     // int64 delivered as int32
    // d_in[2] = edge_attr (unused)
    const int*   batch = (const int*)d_in[3];
    const float* W1    = (const float*)d_in[4];
    const float* as1   = (const float*)d_in[5];
    const float* ad1   = (const float*)d_in[6];
    const float* b1    = (const float*)d_in[7];
    const float* W2    = (const float*)d_in[8];
    const float* as2   = (const float*)d_in[9];
    const float* ad2   = (const float*)d_in[10];
    const float* b2    = (const float*)d_in[11];
    const float* fcw   = (const float*)d_in[12];
    const float* fcb   = (const float*)d_in[13];
    float*       out   = (float*)d_out;

    const int EB = (N_EDGES + 255) / 256;   // 3125
    const int NB = (N_NODES + 127) / 128;   // 391

    k_init<<<NB, 128>>>(x, W1, as1, ad1, W2, as2, ad2, out);
    k_edgeB1<<<EB, 256>>>(ei);
    k_node1_fin<<<NB, 128>>>(W1, b1);
    k_edgeB2<<<EB, 256>>>(ei);
    k_node2_fin<<<NB, 128>>>(batch, W2, b2, fcw, fcb, out);
}